// round 4
// baseline (speedup 1.0000x reference)
#include <cuda_runtime.h>

#define B_ 32
#define S_ 4096
#define H_ 1024
#define NSPANS_ 16
#define NCLS_ 25
#define H4_ (H_ / 4)      // 256 float4 per row
#define CHUNK_ 16         // tokens per pool block
#define NCHUNK_ 4         // ceil(63 / CHUNK_)
#define NBLK_ (B_ * NSPANS_ * NCHUNK_)   // 2048
#define NFC1_ 128                        // fc1 tiles (32 j-tiles x 4 b-groups)

// Persistent scratch. Zero-initialized at load; every call restores zeros at
// its end, so each invocation sees identical starting state.
__device__ float g_pooled[B_ * H_];
__device__ float g_logits[B_ * NCLS_];
__device__ unsigned g_cnt1;
__device__ unsigned g_cnt2;

__device__ __forceinline__ void f4add(float4& a, const float4 b) {
    a.x += b.x; a.y += b.y; a.z += b.z; a.w += b.w;
}

// ---------------------------------------------------------------------------
// Single fused kernel: pool -> (ticket sync) -> fc1+fc2partial -> (ticket
// sync) -> sigmoid + state re-zero.
// grid (NCHUNK, NSPANS, B), block 256.
// ---------------------------------------------------------------------------
__global__ void __launch_bounds__(256)
fused_kernel(const float* __restrict__ emb,
             const int* __restrict__ spans,
             const float* __restrict__ W1,
             const float* __restrict__ b1,
             const float* __restrict__ W2,
             const float* __restrict__ b2,
             float* __restrict__ out) {
    const int tid = threadIdx.x;
    const int b = blockIdx.z;
    const int n = blockIdx.y;
    const int c = blockIdx.x;

    __shared__ float sp[8][H_];   // 32 KB, used in fc1 phase
    __shared__ float s_inv[8];
    __shared__ int ss, se, svalid;
    __shared__ unsigned s_ticket, s_ticket2;

    // ---------------- Phase 1: pool one 16-token chunk of one span ----------
    if (tid == 0) {
        const int* row = spans + b * (NSPANS_ * 2);
        int s = row[2 * n], e = row[2 * n + 1];
        int v = !(s == 0 && e == 0);
        for (int m = 0; m < n && v; m++) {           // torch 'break' semantics
            if (row[2 * m] == 0 && row[2 * m + 1] == 0) v = 0;
        }
        int cs = s + c * CHUNK_;
        int ce = cs + CHUNK_ < e ? cs + CHUNK_ : e;
        ss = cs; se = ce; svalid = v && (cs < e);
    }
    __syncthreads();

    if (svalid) {
        const int s = ss, e = se;
        const float4* base =
            (const float4*)emb + (size_t)b * S_ * H4_ + tid;

        float4 a0 = {0,0,0,0}, a1 = {0,0,0,0}, a2 = {0,0,0,0}, a3 = {0,0,0,0};
        int t = s;
        for (; t + 3 < e; t += 4) {
            f4add(a0, base[(size_t)(t + 0) * H4_]);
            f4add(a1, base[(size_t)(t + 1) * H4_]);
            f4add(a2, base[(size_t)(t + 2) * H4_]);
            f4add(a3, base[(size_t)(t + 3) * H4_]);
        }
        for (; t < e; t++) f4add(a0, base[(size_t)t * H4_]);
        f4add(a0, a1); f4add(a2, a3); f4add(a0, a2);

        float* dst = g_pooled + b * H_ + tid * 4;
        atomicAdd(dst + 0, a0.x);
        atomicAdd(dst + 1, a0.y);
        atomicAdd(dst + 2, a0.z);
        atomicAdd(dst + 3, a0.w);
    }

    // ---------------- Ticket: last NFC1_ finishers become fc1 workers -------
    __threadfence();
    if (tid == 0) s_ticket = atomicAdd(&g_cnt1, 1u);
    __syncthreads();
    const unsigned ticket = s_ticket;
    if (ticket < (unsigned)(NBLK_ - NFC1_)) return;

    if (tid == 0) {
        volatile unsigned* p = &g_cnt1;
        while (*p < (unsigned)NBLK_) { __nanosleep(64); }
    }
    __syncthreads();
    __threadfence();

    // ---------------- Phase 2: fc1 + fc2 partial ----------------------------
    // tile in [0,128): bg = tile & 3 (b-group of 8), jt = tile >> 2 (j-tile)
    const unsigned tile = ticket - (unsigned)(NBLK_ - NFC1_);
    const int bg = (int)(tile & 3u);
    const int jt = (int)(tile >> 2);
    const int lane = tid & 31;
    const int ty = tid >> 5;               // 0..7
    const int j = jt * 32 + lane;
    const int brow = bg * 8 + ty;

    if (tid < 8) {
        const int* row = spans + (bg * 8 + tid) * (NSPANS_ * 2);
        int total = 0;
        #pragma unroll
        for (int m = 0; m < NSPANS_; m++) {
            int a = row[2 * m], e = row[2 * m + 1];
            if (a == 0 && e == 0) break;
            total += e - a;
        }
        s_inv[tid] = 1.0f / (float)total;
    }
    __syncthreads();

    // stage pooled/total into smem (float4)
    {
        const float4* psrc = (const float4*)(g_pooled + bg * 8 * H_);
        float4* pdst = (float4*)&sp[0][0];
        for (int k = tid; k < 8 * H4_; k += 256) {
            float4 v = psrc[k];
            const float inv = s_inv[k >> 8];
            v.x *= inv; v.y *= inv; v.z *= inv; v.w *= inv;
            pdst[k] = v;
        }
    }
    __syncthreads();

    // fc1 dot with 4 independent accumulators
    const float* w = W1 + j;
    const float* p = sp[ty];
    float c0 = 0.f, c1 = 0.f, c2 = 0.f, c3 = 0.f;
    #pragma unroll 4
    for (int i = 0; i < H_; i += 4) {
        c0 += p[i + 0] * w[(size_t)(i + 0) * H_];
        c1 += p[i + 1] * w[(size_t)(i + 1) * H_];
        c2 += p[i + 2] * w[(size_t)(i + 2) * H_];
        c3 += p[i + 3] * w[(size_t)(i + 3) * H_];
    }
    const float h = fmaxf((c0 + c1) + (c2 + c3) + b1[j], 0.f);

    // fc2 partial: broadcast each lane's h; lane c accumulates class c
    float accc = 0.f;
    const int jbase = jt * 32;
    #pragma unroll
    for (int l = 0; l < 32; l++) {
        const float hv = __shfl_sync(0xffffffffu, h, l);
        if (lane < NCLS_)
            accc += hv * W2[(jbase + l) * NCLS_ + lane];
    }
    if (lane < NCLS_)
        atomicAdd(g_logits + brow * NCLS_ + lane, accc);

    // ---------------- Ticket 2: last fc1 block runs the epilogue ------------
    __threadfence();
    if (tid == 0) s_ticket2 = atomicAdd(&g_cnt2, 1u);
    __syncthreads();
    if (s_ticket2 != (unsigned)(NFC1_ - 1)) return;
    __threadfence();

    // ---------------- Phase 3: sigmoid + restore zero state -----------------
    for (int idx = tid; idx < B_ * NCLS_; idx += 256) {
        const float v = g_logits[idx] + b2[idx % NCLS_];
        out[idx] = 1.f / (1.f + __expf(-v));
        g_logits[idx] = 0.f;               // same thread wrote what it read
    }
    {
        float4* pz = (float4*)g_pooled;
        for (int k = tid; k < B_ * H4_; k += 256)
            pz[k] = make_float4(0.f, 0.f, 0.f, 0.f);
    }
    if (tid == 0) { g_cnt1 = 0u; g_cnt2 = 0u; }
}

// ---------------------------------------------------------------------------
extern "C" void kernel_launch(void* const* d_in, const int* in_sizes, int n_in,
                              void* d_out, int out_size) {
    const float* all_emb = (const float*)d_in[0];
    const int*   spans   = (const int*)d_in[1];
    const float* W1      = (const float*)d_in[2];
    const float* b1      = (const float*)d_in[3];
    const float* W2      = (const float*)d_in[4];
    const float* b2      = (const float*)d_in[5];
    float* out = (float*)d_out;

    dim3 grid(NCHUNK_, NSPANS_, B_);
    fused_kernel<<<grid, 256>>>(all_emb, spans, W1, b1, W2, b2, out);
}

// round 5
// speedup vs baseline: 1.4897x; 1.4897x over previous
#include <cuda_runtime.h>

#define B_ 32
#define S_ 4096
#define H_ 1024
#define NSPANS_ 16
#define NCLS_ 25
#define H4_ (H_ / 4)      // 256 float4 per row
#define CHUNK_ 16         // tokens per pool block
#define NCHUNK_ 4         // ceil(63 / CHUNK_)
#define NFC1_ 128         // fc1 tiles (32 j-tiles x 4 b-groups)

// Persistent scratch. Zero-initialized at load; the fc1 epilogue restores
// zeros at the end of every call, so each invocation sees identical state.
__device__ float g_pooled[B_ * H_];
__device__ float g_logits[B_ * NCLS_];
__device__ unsigned g_cnt;

__device__ __forceinline__ void f4add(float4& a, const float4 b) {
    a.x += b.x; a.y += b.y; a.z += b.z; a.w += b.w;
}

// ---------------------------------------------------------------------------
// Kernel 1: span gather-sum. grid (NCHUNK, NSPANS, B), block 256, tiny smem.
// Each block: one 16-token chunk of one span; thread t owns float4 column t.
// Overlapping spans accumulate via atomicAdd (matches cat-then-mean).
// Assumes g_pooled == 0 on entry (restored by previous call's epilogue).
// ---------------------------------------------------------------------------
__global__ void __launch_bounds__(256)
pool_kernel(const float* __restrict__ emb,
            const int* __restrict__ spans,
            float* __restrict__ pooled) {
    const int b = blockIdx.z;
    const int n = blockIdx.y;
    const int c = blockIdx.x;

    __shared__ int ss, se, svalid;
    if (threadIdx.x == 0) {
        const int* row = spans + b * (NSPANS_ * 2);
        int s = row[2 * n], e = row[2 * n + 1];
        int v = !(s == 0 && e == 0);
        for (int m = 0; m < n && v; m++) {           // torch 'break' semantics
            if (row[2 * m] == 0 && row[2 * m + 1] == 0) v = 0;
        }
        int cs = s + c * CHUNK_;
        int ce = cs + CHUNK_ < e ? cs + CHUNK_ : e;
        ss = cs; se = ce; svalid = v && (cs < e);
    }
    __syncthreads();
    if (!svalid) return;

    const int s = ss, e = se;
    const float4* base = (const float4*)emb + (size_t)b * S_ * H4_ + threadIdx.x;

    float4 a0 = {0,0,0,0}, a1 = {0,0,0,0}, a2 = {0,0,0,0}, a3 = {0,0,0,0};
    int t = s;
    for (; t + 3 < e; t += 4) {
        f4add(a0, base[(size_t)(t + 0) * H4_]);
        f4add(a1, base[(size_t)(t + 1) * H4_]);
        f4add(a2, base[(size_t)(t + 2) * H4_]);
        f4add(a3, base[(size_t)(t + 3) * H4_]);
    }
    for (; t < e; t++) f4add(a0, base[(size_t)t * H4_]);
    f4add(a0, a1); f4add(a2, a3); f4add(a0, a2);

    float* dst = pooled + b * H_ + threadIdx.x * 4;
    atomicAdd(dst + 0, a0.x);
    atomicAdd(dst + 1, a0.y);
    atomicAdd(dst + 2, a0.z);
    atomicAdd(dst + 3, a0.w);
}

// ---------------------------------------------------------------------------
// Kernel 2: fc1 + fc2-partial + (last-block) sigmoid epilogue + state re-zero.
// grid 128 (tile = blockIdx.x: bg = tile&3 b-group, jt = tile>>2 j-tile),
// block (32,8). One wave (128 blocks, 33KB smem -> 6/SM cap, 148 SMs).
// ---------------------------------------------------------------------------
__global__ void __launch_bounds__(256)
fc1_kernel(const int* __restrict__ spans,
           const float* __restrict__ W1,
           const float* __restrict__ b1,
           const float* __restrict__ W2,
           const float* __restrict__ b2,
           float* __restrict__ out) {
    const int tile = blockIdx.x;
    const int bg = tile & 3;
    const int jt = tile >> 2;
    const int lane = threadIdx.x;
    const int ty = threadIdx.y;
    const int tid = ty * 32 + lane;
    const int j = jt * 32 + lane;
    const int brow = bg * 8 + ty;

    __shared__ float sp[8][H_];   // 32 KB
    __shared__ float s_inv[8];
    __shared__ unsigned s_ticket;

    if (tid < 8) {
        const int* row = spans + (bg * 8 + tid) * (NSPANS_ * 2);
        int total = 0;
        #pragma unroll
        for (int m = 0; m < NSPANS_; m++) {
            int a = row[2 * m], e = row[2 * m + 1];
            if (a == 0 && e == 0) break;
            total += e - a;
        }
        s_inv[tid] = 1.0f / (float)total;
    }
    __syncthreads();

    // stage pooled/total into smem (float4)
    {
        const float4* psrc = (const float4*)(g_pooled + bg * 8 * H_);
        float4* pdst = (float4*)&sp[0][0];
        for (int k = tid; k < 8 * H4_; k += 256) {
            float4 v = psrc[k];
            const float inv = s_inv[k >> 8];
            v.x *= inv; v.y *= inv; v.z *= inv; v.w *= inv;
            pdst[k] = v;
        }
    }
    __syncthreads();

    // fc1 dot with 4 independent accumulators
    const float* w = W1 + j;
    const float* p = sp[ty];
    float c0 = 0.f, c1 = 0.f, c2 = 0.f, c3 = 0.f;
    #pragma unroll 4
    for (int i = 0; i < H_; i += 4) {
        c0 += p[i + 0] * w[(size_t)(i + 0) * H_];
        c1 += p[i + 1] * w[(size_t)(i + 1) * H_];
        c2 += p[i + 2] * w[(size_t)(i + 2) * H_];
        c3 += p[i + 3] * w[(size_t)(i + 3) * H_];
    }
    const float h = fmaxf((c0 + c1) + (c2 + c3) + b1[j], 0.f);

    // fc2 partial: broadcast each lane's h; lane c accumulates class c
    float accc = 0.f;
    const int jbase = jt * 32;
    #pragma unroll
    for (int l = 0; l < 32; l++) {
        const float hv = __shfl_sync(0xffffffffu, h, l);
        if (lane < NCLS_)
            accc += hv * W2[(jbase + l) * NCLS_ + lane];
    }
    if (lane < NCLS_)
        atomicAdd(g_logits + brow * NCLS_ + lane, accc);

    // ---- ticket: the block drawing NFC1_-1 is provably last; no spin -------
    __threadfence();
    __syncthreads();
    if (tid == 0) s_ticket = atomicAdd(&g_cnt, 1u);
    __syncthreads();
    if (s_ticket != (unsigned)(NFC1_ - 1)) return;

    // ---- epilogue: sigmoid + restore zero state -----------------------------
    for (int idx = tid; idx < B_ * NCLS_; idx += 256) {
        const float v = __ldcg(g_logits + idx) + b2[idx % NCLS_];
        out[idx] = 1.f / (1.f + __expf(-v));
        g_logits[idx] = 0.f;
    }
    {
        float4* pz = (float4*)g_pooled;
        for (int k = tid; k < B_ * H4_; k += 256)
            pz[k] = make_float4(0.f, 0.f, 0.f, 0.f);
    }
    if (tid == 0) g_cnt = 0u;
}

// ---------------------------------------------------------------------------
extern "C" void kernel_launch(void* const* d_in, const int* in_sizes, int n_in,
                              void* d_out, int out_size) {
    const float* all_emb = (const float*)d_in[0];
    const int*   spans   = (const int*)d_in[1];
    const float* W1      = (const float*)d_in[2];
    const float* b1      = (const float*)d_in[3];
    const float* W2      = (const float*)d_in[4];
    const float* b2      = (const float*)d_in[5];
    float* out = (float*)d_out;

    float* pooled;
    cudaGetSymbolAddress((void**)&pooled, g_pooled);

    {
        dim3 grid(NCHUNK_, NSPANS_, B_);
        pool_kernel<<<grid, 256>>>(all_emb, spans, pooled);
    }
    {
        dim3 block(32, 8);
        fc1_kernel<<<NFC1_, block>>>(spans, W1, b1, W2, b2, out);
    }
}

// round 6
// speedup vs baseline: 1.8200x; 1.2217x over previous
#include <cuda_runtime.h>

#define B_ 32
#define S_ 4096
#define H_ 1024
#define NSPANS_ 16
#define NCLS_ 25
#define H4_ (H_ / 4)      // 256 float4 per row
#define CHUNK_ 16         // tokens per pool block
#define NCHUNK_ 4         // ceil(63 / CHUNK_)
#define NFC1_ 128         // fc1 tiles (32 j-tiles x 4 b-groups)
#define KT_ 32            // K-tile rows in fc1

// Persistent scratch. Zero-initialized at load; the fc1 epilogue restores
// zeros at the end of every call, so each invocation sees identical state.
__device__ float g_pooled[B_ * H_];
__device__ float g_logits[B_ * NCLS_];
__device__ unsigned g_cnt;

__device__ __forceinline__ void f4add(float4& a, const float4 b) {
    a.x += b.x; a.y += b.y; a.z += b.z; a.w += b.w;
}

// ---------------------------------------------------------------------------
// Kernel 1: span gather-sum. grid (NCHUNK, NSPANS, B), block 256, tiny smem.
// Each block: one 16-token chunk of one span; thread t owns float4 column t.
// Overlapping spans accumulate via atomicAdd (matches cat-then-mean).
// Assumes g_pooled == 0 on entry (restored by previous call's epilogue).
// ---------------------------------------------------------------------------
__global__ void __launch_bounds__(256)
pool_kernel(const float* __restrict__ emb,
            const int* __restrict__ spans,
            float* __restrict__ pooled) {
    const int b = blockIdx.z;
    const int n = blockIdx.y;
    const int c = blockIdx.x;

    __shared__ int ss, se, svalid;
    if (threadIdx.x == 0) {
        const int* row = spans + b * (NSPANS_ * 2);
        int s = row[2 * n], e = row[2 * n + 1];
        int v = !(s == 0 && e == 0);
        for (int m = 0; m < n && v; m++) {           // torch 'break' semantics
            if (row[2 * m] == 0 && row[2 * m + 1] == 0) v = 0;
        }
        int cs = s + c * CHUNK_;
        int ce = cs + CHUNK_ < e ? cs + CHUNK_ : e;
        ss = cs; se = ce; svalid = v && (cs < e);
    }
    __syncthreads();
    if (!svalid) return;

    const int s = ss, e = se;
    const float4* base = (const float4*)emb + (size_t)b * S_ * H4_ + threadIdx.x;

    float4 a0 = {0,0,0,0}, a1 = {0,0,0,0}, a2 = {0,0,0,0}, a3 = {0,0,0,0};
    int t = s;
    for (; t + 3 < e; t += 4) {
        f4add(a0, base[(size_t)(t + 0) * H4_]);
        f4add(a1, base[(size_t)(t + 1) * H4_]);
        f4add(a2, base[(size_t)(t + 2) * H4_]);
        f4add(a3, base[(size_t)(t + 3) * H4_]);
    }
    for (; t < e; t++) f4add(a0, base[(size_t)t * H4_]);
    f4add(a0, a1); f4add(a2, a3); f4add(a0, a2);

    float* dst = pooled + b * H_ + threadIdx.x * 4;
    atomicAdd(dst + 0, a0.x);
    atomicAdd(dst + 1, a0.y);
    atomicAdd(dst + 2, a0.z);
    atomicAdd(dst + 3, a0.w);
}

// ---------------------------------------------------------------------------
// Kernel 2: smem-tiled fc1 + fc2-partial + (last-block) sigmoid epilogue.
// grid 128 (tile = blockIdx.x: bg = tile&3 b-group, jt = tile>>2 j-tile),
// block (32,8). W1 streamed through double-buffered 32x32 smem tiles:
// 256 threads each fetch one float4 per tile (coalesced, block-wide MLP).
// ---------------------------------------------------------------------------
__global__ void __launch_bounds__(256)
fc1_kernel(const int* __restrict__ spans,
           const float* __restrict__ W1,
           const float* __restrict__ b1,
           const float* __restrict__ W2,
           const float* __restrict__ b2,
           float* __restrict__ out) {
    const int tile = blockIdx.x;
    const int bg = tile & 3;
    const int jt = tile >> 2;
    const int lane = threadIdx.x;
    const int ty = threadIdx.y;
    const int tid = ty * 32 + lane;
    const int j = jt * 32 + lane;
    const int brow = bg * 8 + ty;

    __shared__ float sp[8][H_];          // 32 KB
    __shared__ float wt[2][KT_][32];     // 8 KB double-buffered W1 tile
    __shared__ float s_inv[8];
    __shared__ unsigned s_ticket;

    if (tid < 8) {
        const int* row = spans + (bg * 8 + tid) * (NSPANS_ * 2);
        int total = 0;
        #pragma unroll
        for (int m = 0; m < NSPANS_; m++) {
            int a = row[2 * m], e = row[2 * m + 1];
            if (a == 0 && e == 0) break;
            total += e - a;
        }
        s_inv[tid] = 1.0f / (float)total;
    }
    __syncthreads();

    // stage pooled/total into smem (float4)
    {
        const float4* psrc = (const float4*)(g_pooled + bg * 8 * H_);
        float4* pdst = (float4*)&sp[0][0];
        for (int k = tid; k < 8 * H4_; k += 256) {
            float4 v = psrc[k];
            const float inv = s_inv[k >> 8];
            v.x *= inv; v.y *= inv; v.z *= inv; v.w *= inv;
            pdst[k] = v;
        }
    }

    // W1 tile fetch geometry: thread -> (row within tile, float4 column)
    const int wrow = tid >> 3;           // 0..31
    const int wcol = (tid & 7) * 4;      // 0,4,...,28
    const float* wptr = W1 + (size_t)wrow * H_ + jt * 32 + wcol;

    // prologue: tile 0
    float4 r = *(const float4*)(wptr);
    *(float4*)&wt[0][wrow][wcol] = r;
    __syncthreads();

    const float* p = sp[ty];
    float c0 = 0.f, c1 = 0.f, c2 = 0.f, c3 = 0.f;

    #pragma unroll 1
    for (int t = 0; t < H_ / KT_; t++) {
        // prefetch next tile into registers
        if (t + 1 < H_ / KT_)
            r = *(const float4*)(wptr + (size_t)(t + 1) * KT_ * H_);

        const float* wk = &wt[t & 1][0][lane];
        const float* pk = p + t * KT_;
        #pragma unroll
        for (int k = 0; k < KT_; k += 4) {
            c0 += pk[k + 0] * wk[(k + 0) * 32];
            c1 += pk[k + 1] * wk[(k + 1) * 32];
            c2 += pk[k + 2] * wk[(k + 2) * 32];
            c3 += pk[k + 3] * wk[(k + 3) * 32];
        }

        if (t + 1 < H_ / KT_)
            *(float4*)&wt[(t + 1) & 1][wrow][wcol] = r;
        __syncthreads();
    }
    const float h = fmaxf((c0 + c1) + (c2 + c3) + b1[j], 0.f);

    // fc2 partial: broadcast each lane's h; lane c accumulates class c
    float accc = 0.f;
    const int jbase = jt * 32;
    #pragma unroll
    for (int l = 0; l < 32; l++) {
        const float hv = __shfl_sync(0xffffffffu, h, l);
        if (lane < NCLS_)
            accc += hv * W2[(jbase + l) * NCLS_ + lane];
    }
    if (lane < NCLS_)
        atomicAdd(g_logits + brow * NCLS_ + lane, accc);

    // ---- ticket: the block drawing NFC1_-1 is provably last; no spin -------
    __threadfence();
    __syncthreads();
    if (tid == 0) s_ticket = atomicAdd(&g_cnt, 1u);
    __syncthreads();
    if (s_ticket != (unsigned)(NFC1_ - 1)) return;

    // ---- epilogue: sigmoid + restore zero state -----------------------------
    for (int idx = tid; idx < B_ * NCLS_; idx += 256) {
        const float v = __ldcg(g_logits + idx) + b2[idx % NCLS_];
        out[idx] = 1.f / (1.f + __expf(-v));
        g_logits[idx] = 0.f;
    }
    {
        float4* pz = (float4*)g_pooled;
        for (int k = tid; k < B_ * H4_; k += 256)
            pz[k] = make_float4(0.f, 0.f, 0.f, 0.f);
    }
    if (tid == 0) g_cnt = 0u;
}

// ---------------------------------------------------------------------------
extern "C" void kernel_launch(void* const* d_in, const int* in_sizes, int n_in,
                              void* d_out, int out_size) {
    const float* all_emb = (const float*)d_in[0];
    const int*   spans   = (const int*)d_in[1];
    const float* W1      = (const float*)d_in[2];
    const float* b1      = (const float*)d_in[3];
    const float* W2      = (const float*)d_in[4];
    const float* b2      = (const float*)d_in[5];
    float* out = (float*)d_out;

    float* pooled;
    cudaGetSymbolAddress((void**)&pooled, g_pooled);

    {
        dim3 grid(NCHUNK_, NSPANS_, B_);
        pool_kernel<<<grid, 256>>>(all_emb, spans, pooled);
    }
    {
        dim3 block(32, 8);
        fc1_kernel<<<NFC1_, block>>>(spans, W1, b1, W2, b2, out);
    }
}